// round 9
// baseline (speedup 1.0000x reference)
#include <cuda_runtime.h>
#include <cuda_fp16.h>
#include <cstdint>

#define H_ 3
#define L_ 2
#define B_ 16
#define S_ 512
#define D_ 512
#define F_ (H_ * L_ * D_)   // 3072

// Scratch (no cudaMalloc allowed) — fp16 operand buffers
__device__ __align__(16) __half g_adjH[(size_t)H_ * B_ * S_ * S_];  // 25 MB
__device__ __align__(16) __half g_AxH[(size_t)H_ * B_ * S_ * D_];   // 25 MB
__device__ __align__(16) __half g_finH[(size_t)B_ * S_ * F_];       // 50 MB
__device__ __align__(16) __half g_XTH[(size_t)H_ * B_ * D_ * S_];   // 25 MB
__device__ __align__(16) __half g_X0TH[(size_t)B_ * D_ * S_];       // 8 MB
__device__ __align__(16) __half g_WgH[(size_t)H_ * L_ * D_ * D_];   // 3 MB
__device__ __align__(16) __half g_WoH[(size_t)D_ * F_];             // 3 MB
__device__ float g_denom[H_ * B_ * S_];                             // 96 KB

// ---------------------------------------------------------------------------
__device__ __forceinline__ uint32_t smem_u32(const void* p) {
    uint32_t a;
    asm("{ .reg .u64 t; cvta.to.shared.u64 t, %1; cvt.u32.u64 %0, t; }" : "=r"(a) : "l"(p));
    return a;
}
#define CP_ASYNC16(dst, src) \
    asm volatile("cp.async.cg.shared.global [%0], [%1], 16;" :: "r"(dst), "l"(src))
#define CP_COMMIT() asm volatile("cp.async.commit_group;")
#define CP_WAIT(n)  asm volatile("cp.async.wait_group %0;" :: "n"(n))

#define LDSM4(r0, r1, r2, r3, addr) \
    asm volatile("ldmatrix.sync.aligned.m8n8.x4.shared.b16 {%0,%1,%2,%3}, [%4];" \
        : "=r"(r0), "=r"(r1), "=r"(r2), "=r"(r3) : "r"(addr))

#define MMA_F16(c, a, b0, b1) \
    asm volatile("mma.sync.aligned.m16n8k16.row.col.f32.f16.f16.f32 " \
        "{%0,%1,%2,%3}, {%4,%5,%6,%7}, {%8,%9}, {%0,%1,%2,%3};" \
        : "+f"((c)[0]), "+f"((c)[1]), "+f"((c)[2]), "+f"((c)[3]) \
        : "r"((a)[0]), "r"((a)[1]), "r"((a)[2]), "r"((a)[3]), \
          "r"(b0), "r"(b1))

__device__ __forceinline__ __half toh(float x)  { return __float2half_rn(x); }
__device__ __forceinline__ __half toh(__half x) { return x; }

// ---------------------------------------------------------------------------
// Per row (h,b,s): den = 1 + sum_t adj (exact fp32), adjH = half(adj)
// ---------------------------------------------------------------------------
__global__ void denom_round_kernel(const float* __restrict__ adj,
                                   float* __restrict__ den,
                                   __half* __restrict__ adjH)
{
    int gw = (blockIdx.x * blockDim.x + threadIdx.x) >> 5;
    int lane = threadIdx.x & 31;
    if (gw >= H_ * B_ * S_) return;
    const float4* p = (const float4*)(adj + (long)gw * S_);
    __half2* q = (__half2*)(adjH + (long)gw * S_);
    float s = 0.f;
    #pragma unroll 2
    for (int i = lane; i < S_ / 4; i += 32) {
        float4 v = p[i];
        s += v.x + v.y + v.z + v.w;
        q[2 * i]     = __floats2half2_rn(v.x, v.y);
        q[2 * i + 1] = __floats2half2_rn(v.z, v.w);
    }
    #pragma unroll
    for (int o = 16; o > 0; o >>= 1) s += __shfl_xor_sync(0xffffffffu, s, o);
    if (lane == 0) den[gw] = s + 1.0f;
}

__global__ void roundcopy_half(const float* __restrict__ src,
                               __half* __restrict__ dst, int n4)
{
    int i = blockIdx.x * blockDim.x + threadIdx.x;
    if (i >= n4) return;
    float4 v = ((const float4*)src)[i];
    ((__half2*)dst)[2 * i]     = __floats2half2_rn(v.x, v.y);
    ((__half2*)dst)[2 * i + 1] = __floats2half2_rn(v.z, v.w);
}

// ---------------------------------------------------------------------------
// XT[h][b][d][s] = half( X[...][s][d] )
// ---------------------------------------------------------------------------
template <typename T>
__global__ void transpose_kernel(const T* __restrict__ X, int ldx,
                                 long xHead, long xBatch,
                                 __half* __restrict__ XT, long tHead)
{
    __shared__ __half t[32][33];
    int z = blockIdx.z;
    int hz = z >> 4, bz = z & 15;
    int s0 = blockIdx.x * 32, d0 = blockIdx.y * 32;
    const T* Xb = X + (long)hz * xHead + (long)bz * xBatch;
    __half* Tb = XT + (long)hz * tHead + (long)bz * D_ * S_;
    int tx = threadIdx.x, ty = threadIdx.y;  // 32 x 8
    #pragma unroll
    for (int i = 0; i < 32; i += 8)
        t[ty + i][tx] = toh(Xb[(long)(s0 + ty + i) * ldx + d0 + tx]);
    __syncthreads();
    #pragma unroll
    for (int i = 0; i < 32; i += 8)
        Tb[(long)(d0 + ty + i) * S_ + s0 + tx] = t[tx][ty + i];
}

// ---------------------------------------------------------------------------
// FP16 mma.sync GEMM (fp32 accum): C[M,N] = A[M,K] * B[N,K]^T, K-major halves.
// CTA 128x128 with 4 warps (2x2 grid of 64x64 warp tiles), 128 threads,
// 3-stage cp.async, single barrier per k-tile, 2 CTAs/SM.
// z encodes (head = z>>4, batch = z&15).
// MODE 0: Chalf = acc + epi[m][n]             (epi fp32 or fp16 per EPI_HALF)
// MODE 1: Chalf = relu((acc + biasScale*bias[n]) / denom[z,m])
// MODE 2: Cfloat = acc + bias[n] + epi[m][n]  (epi fp32)
// ---------------------------------------------------------------------------
constexpr int BM = 128, BN = 128, BK = 64;        // BK in halves (128 bytes)
constexpr int LDSROW = 72;                        // halves; 144B stride -> conflict-free
constexpr int STAGE_HALVES = 2 * BM * LDSROW;     // A + B = 18432
constexpr int STAGE_BYTES = STAGE_HALVES * 2;     // 36864
constexpr int NSTAGE = 3;
constexpr int SMEM_SZ = NSTAGE * STAGE_BYTES;     // 110592

template <int MODE, bool EPI_HALF>
__global__ __launch_bounds__(128, 2)
void mma_gemm(const __half* __restrict__ A, const __half* __restrict__ Bm,
              void* __restrict__ C,
              int K, int lda, int ldb, int ldc,
              long aHead, long aBatch, long bHead, long bBatch,
              long cHead, long cBatch,
              const void* __restrict__ epi, int epiLd, long epiHead, long epiBatch,
              const float* __restrict__ bias, long biasHead, float biasScale,
              const float* __restrict__ denom, int denomStride)
{
    extern __shared__ char smemc[];
    const int tid = threadIdx.x;
    const int wid = tid >> 5, lane = tid & 31;
    const int bx = blockIdx.x, by = blockIdx.y, z = blockIdx.z;
    const int hz = z >> 4, bz = z & 15;

    const uint32_t sbase = smem_u32(smemc);

    const __half* Ab = A + (long)hz * aHead + (long)bz * aBatch + (long)(by * BM) * lda;
    const __half* Bb = Bm + (long)hz * bHead + (long)bz * bBatch + (long)(bx * BN) * ldb;

    // cp.async: 128 threads, each owns one A row and one B row (8 x 16B each)
    auto load_stage = [&](int s, int kt) {
        const long k0 = (long)kt * BK;
        const __half* ag = Ab + (long)tid * lda + k0;
        const __half* bg = Bb + (long)tid * ldb + k0;
        uint32_t da = sbase + (uint32_t)(s * STAGE_BYTES) + (uint32_t)(tid * LDSROW) * 2u;
        uint32_t db = da + (uint32_t)(BM * LDSROW) * 2u;
        #pragma unroll
        for (int i = 0; i < 8; ++i) {
            CP_ASYNC16(da + i * 16u, ag + i * 8);
            CP_ASYNC16(db + i * 16u, bg + i * 8);
        }
    };

    // warp tiling: 2 (m) x 2 (n); each warp 64x64
    const int m0 = (wid & 1) * 64;
    const int n0 = (wid >> 1) * 64;
    const int lq = lane >> 2;
    const int lr = lane & 3;

    // ldmatrix base addresses (stage 0, ks = 0)
    const uint32_t aAddr0 = sbase
        + (uint32_t)((m0 + ((lane >> 3) & 1) * 8 + (lane & 7)) * LDSROW) * 2u
        + (uint32_t)(lane >> 4) * 16u;
    const uint32_t bAddr0 = sbase + (uint32_t)(BM * LDSROW) * 2u
        + (uint32_t)((n0 + (lane >> 4) * 8 + (lane & 7)) * LDSROW) * 2u
        + (uint32_t)((lane >> 3) & 1) * 16u;

    float c[4][8][4];
    #pragma unroll
    for (int mi = 0; mi < 4; ++mi)
        #pragma unroll
        for (int ni = 0; ni < 8; ++ni)
            #pragma unroll
            for (int j = 0; j < 4; ++j) c[mi][ni][j] = 0.f;

    const int numK = K >> 6;   // >= 8 for all our GEMMs

    load_stage(0, 0); CP_COMMIT();
    load_stage(1, 1); CP_COMMIT();

    for (int kt = 0; kt < numK; ++kt) {
        if (kt + 1 < numK) { CP_WAIT(1); } else { CP_WAIT(0); }
        __syncthreads();   // single barrier per k-tile (3-stage WAR covered)
        if (kt + 2 < numK) {
            load_stage((kt + 2) % NSTAGE, kt + 2);
            CP_COMMIT();
        }

        const uint32_t sOff = (uint32_t)(kt % NSTAGE) * STAGE_BYTES;
        #pragma unroll
        for (int ks = 0; ks < 4; ++ks) {          // k16 steps within BK=64
            const uint32_t kOff = sOff + (uint32_t)ks * 32u;   // 16 halves
            uint32_t a[4][4], b[4][4];
            #pragma unroll
            for (int p = 0; p < 4; ++p)
                LDSM4(b[p][0], b[p][1], b[p][2], b[p][3],
                      bAddr0 + kOff + (uint32_t)p * (16u * LDSROW * 2u));
            #pragma unroll
            for (int mi = 0; mi < 4; ++mi)
                LDSM4(a[mi][0], a[mi][1], a[mi][2], a[mi][3],
                      aAddr0 + kOff + (uint32_t)mi * (16u * LDSROW * 2u));
            #pragma unroll
            for (int mi = 0; mi < 4; ++mi)
                #pragma unroll
                for (int ni = 0; ni < 8; ++ni)
                    MMA_F16(c[mi][ni], a[mi], b[ni >> 1][(ni & 1) * 2],
                            b[ni >> 1][(ni & 1) * 2 + 1]);
        }
    }

    // ---------------- epilogue ----------------
    const float* biasP = (MODE == 1 || MODE == 2) ? (bias + (long)hz * biasHead) : nullptr;

    #pragma unroll
    for (int mi = 0; mi < 4; ++mi) {
        const int r0 = by * BM + m0 + mi * 16 + lq;
        float invd0 = 1.f, invd1 = 1.f;
        if (MODE == 1) {
            invd0 = 1.0f / denom[(long)z * denomStride + r0];
            invd1 = 1.0f / denom[(long)z * denomStride + r0 + 8];
        }
        #pragma unroll
        for (int ni = 0; ni < 8; ++ni) {
            const int col = bx * BN + n0 + ni * 8 + 2 * lr;
            float v00 = c[mi][ni][0], v01 = c[mi][ni][1];
            float v10 = c[mi][ni][2], v11 = c[mi][ni][3];
            if (MODE == 0) {
                if (EPI_HALF) {
                    const __half* Eb = (const __half*)epi
                        + (long)hz * epiHead + (long)bz * epiBatch;
                    float2 e0 = __half22float2(*(const __half2*)(Eb + (long)r0 * epiLd + col));
                    float2 e1 = __half22float2(*(const __half2*)(Eb + (long)(r0 + 8) * epiLd + col));
                    v00 += e0.x; v01 += e0.y; v10 += e1.x; v11 += e1.y;
                } else {
                    const float* Eb = (const float*)epi
                        + (long)hz * epiHead + (long)bz * epiBatch;
                    float2 e0 = *(const float2*)(Eb + (long)r0 * epiLd + col);
                    float2 e1 = *(const float2*)(Eb + (long)(r0 + 8) * epiLd + col);
                    v00 += e0.x; v01 += e0.y; v10 += e1.x; v11 += e1.y;
                }
                __half* Cb = (__half*)C + (long)hz * cHead + (long)bz * cBatch;
                *(__half2*)(Cb + (long)r0 * ldc + col)       = __floats2half2_rn(v00, v01);
                *(__half2*)(Cb + (long)(r0 + 8) * ldc + col) = __floats2half2_rn(v10, v11);
            } else if (MODE == 1) {
                const float b0 = biasScale * biasP[col];
                const float b1 = biasScale * biasP[col + 1];
                v00 = fmaxf((v00 + b0) * invd0, 0.f);
                v01 = fmaxf((v01 + b1) * invd0, 0.f);
                v10 = fmaxf((v10 + b0) * invd1, 0.f);
                v11 = fmaxf((v11 + b1) * invd1, 0.f);
                __half* Cb = (__half*)C + (long)hz * cHead + (long)bz * cBatch;
                *(__half2*)(Cb + (long)r0 * ldc + col)       = __floats2half2_rn(v00, v01);
                *(__half2*)(Cb + (long)(r0 + 8) * ldc + col) = __floats2half2_rn(v10, v11);
            } else {  // MODE 2: fp32 output, fp32 epi (residual) + bias
                const float* Eb = (const float*)epi;
                float2 e0 = *(const float2*)(Eb + (long)r0 * epiLd + col);
                float2 e1 = *(const float2*)(Eb + (long)(r0 + 8) * epiLd + col);
                const float b0 = biasP[col], b1 = biasP[col + 1];
                v00 += e0.x + b0; v01 += e0.y + b1;
                v10 += e1.x + b0; v11 += e1.y + b1;
                float* Cb = (float*)C;
                float2 w0 = {v00, v01}, w1 = {v10, v11};
                *(float2*)(Cb + (long)r0 * ldc + col) = w0;
                *(float2*)(Cb + (long)(r0 + 8) * ldc + col) = w1;
            }
        }
    }
}

// ---------------------------------------------------------------------------
extern "C" void kernel_launch(void* const* d_in, const int* in_sizes, int n_in,
                              void* d_out, int out_size)
{
    const float* adj = (const float*)d_in[0];   // [H,B,S,S]
    const float* x0  = (const float*)d_in[1];   // [B,S,D]
    const float* Wg  = (const float*)d_in[4];   // [H*L, D, D]
    const float* bg  = (const float*)d_in[5];   // [H*L, D]
    const float* Wo  = (const float*)d_in[6];   // [D, F]
    const float* bo  = (const float*)d_in[7];   // [D]
    float* out = (float*)d_out;                 // [B,S,D]

    __half *adjH, *AxH, *finH, *XTH, *X0TH, *WgH, *WoH;
    float* den;
    cudaGetSymbolAddress((void**)&adjH, g_adjH);
    cudaGetSymbolAddress((void**)&AxH,  g_AxH);
    cudaGetSymbolAddress((void**)&finH, g_finH);
    cudaGetSymbolAddress((void**)&XTH,  g_XTH);
    cudaGetSymbolAddress((void**)&X0TH, g_X0TH);
    cudaGetSymbolAddress((void**)&WgH,  g_WgH);
    cudaGetSymbolAddress((void**)&WoH,  g_WoH);
    cudaGetSymbolAddress((void**)&den,  g_denom);

    cudaFuncSetAttribute(mma_gemm<0, false>, cudaFuncAttributeMaxDynamicSharedMemorySize, SMEM_SZ);
    cudaFuncSetAttribute(mma_gemm<0, true>,  cudaFuncAttributeMaxDynamicSharedMemorySize, SMEM_SZ);
    cudaFuncSetAttribute(mma_gemm<1, false>, cudaFuncAttributeMaxDynamicSharedMemorySize, SMEM_SZ);
    cudaFuncSetAttribute(mma_gemm<2, false>, cudaFuncAttributeMaxDynamicSharedMemorySize, SMEM_SZ);

    // ---- prep: denom + fp16 operand copies ----
    denom_round_kernel<<<(H_ * B_ * S_) / 8, 256>>>(adj, den, adjH);
    roundcopy_half<<<(H_ * L_ * D_ * D_ / 4 + 255) / 256, 256>>>(Wg, WgH, H_ * L_ * D_ * D_ / 4);
    roundcopy_half<<<(D_ * F_ / 4 + 255) / 256, 256>>>(Wo, WoH, D_ * F_ / 4);
    transpose_kernel<float><<<dim3(16, 16, B_), dim3(32, 8)>>>(
        x0, D_, 0, (long)S_ * D_, X0TH, 0);

    const long SS = (long)S_ * S_, SD = (long)S_ * D_, SF = (long)S_ * F_;
    const long DS = (long)D_ * S_, DD = (long)D_ * D_;

    for (int l = 0; l < L_; ++l) {
        // GEMM1 (all heads): AxH[h] = adj[h] @ X + X
        if (l == 0) {
            mma_gemm<0, false><<<dim3(4, 4, H_ * B_), 128, SMEM_SZ>>>(
                adjH, X0TH, AxH,
                S_, S_, S_, D_,
                (long)B_ * SS, SS, 0, DS, (long)B_ * SD, SD,
                x0, D_, 0, SD,
                nullptr, 0, 0.f,
                nullptr, 0);
        } else {
            mma_gemm<0, true><<<dim3(4, 4, H_ * B_), 128, SMEM_SZ>>>(
                adjH, XTH, AxH,
                S_, S_, S_, D_,
                (long)B_ * SS, SS, (long)B_ * DS, DS, (long)B_ * SD, SD,
                finH, F_, (long)L_ * D_, SF,   // epi = prev layer output (fp16)
                nullptr, 0, 0.f,
                nullptr, 0);
        }

        // GEMM2 (all heads): finH[.., (h*L+l)*D ..] = relu((AxH @ Wg^T + 2b)/den)
        mma_gemm<1, false><<<dim3(4, 4, H_ * B_), 128, SMEM_SZ>>>(
            AxH, WgH + (long)l * DD, finH + (long)l * D_,
            D_, D_, D_, F_,
            (long)B_ * SD, SD, (long)L_ * DD, 0, (long)L_ * D_, SF,
            nullptr, 0, 0, 0,
            bg + (long)l * D_, (long)L_ * D_, 2.0f,
            den, S_);

        // layer-0 outputs -> transposed fp16 for layer-1 GEMM1 B operand
        if (l == 0)
            transpose_kernel<__half><<<dim3(16, 16, H_ * B_), dim3(32, 8)>>>(
                finH, F_, (long)L_ * D_, SF, XTH, (long)B_ * DS);
    }

    // Final: out = finH @ Wo^T + bo + x0   (M = B*S = 8192, K = F, fp32 out)
    mma_gemm<2, false><<<dim3(4, 64, 1), 128, SMEM_SZ>>>(
        finH, WoH, out,
        F_, F_, F_, D_,
        0, 0, 0, 0, 0, 0,
        x0, D_, 0, 0,
        bo, 0, 1.0f,
        nullptr, 0);
}

// round 11
// speedup vs baseline: 1.1841x; 1.1841x over previous
#include <cuda_runtime.h>
#include <cuda_fp16.h>
#include <cstdint>

#define H_ 3
#define L_ 2
#define B_ 16
#define S_ 512
#define D_ 512
#define F_ (H_ * L_ * D_)   // 3072

// Scratch (no cudaMalloc allowed) — fp16 operand buffers
__device__ __align__(16) __half g_adjH[(size_t)H_ * B_ * S_ * S_];  // 25 MB
__device__ __align__(16) __half g_AxH[(size_t)H_ * B_ * S_ * D_];   // 25 MB
__device__ __align__(16) __half g_finH[(size_t)B_ * S_ * F_];       // 50 MB
__device__ __align__(16) __half g_XTH[(size_t)H_ * B_ * D_ * S_];   // 25 MB
__device__ __align__(16) __half g_X0TH[(size_t)B_ * D_ * S_];       // 8 MB
__device__ __align__(16) __half g_WgH[(size_t)H_ * L_ * D_ * D_];   // 3 MB
__device__ __align__(16) __half g_WoH[(size_t)D_ * F_];             // 3 MB
__device__ float g_denom[H_ * B_ * S_];                             // 96 KB

// ---------------------------------------------------------------------------
__device__ __forceinline__ uint32_t smem_u32(const void* p) {
    uint32_t a;
    asm("{ .reg .u64 t; cvta.to.shared.u64 t, %1; cvt.u32.u64 %0, t; }" : "=r"(a) : "l"(p));
    return a;
}
#define CP_ASYNC16(dst, src) \
    asm volatile("cp.async.cg.shared.global [%0], [%1], 16;" :: "r"(dst), "l"(src))
#define CP_COMMIT() asm volatile("cp.async.commit_group;")
#define CP_WAIT(n)  asm volatile("cp.async.wait_group %0;" :: "n"(n))

#define LDSM4(r0, r1, r2, r3, addr) \
    asm volatile("ldmatrix.sync.aligned.m8n8.x4.shared.b16 {%0,%1,%2,%3}, [%4];" \
        : "=r"(r0), "=r"(r1), "=r"(r2), "=r"(r3) : "r"(addr))

#define MMA_F16(c, a, b0, b1) \
    asm volatile("mma.sync.aligned.m16n8k16.row.col.f32.f16.f16.f32 " \
        "{%0,%1,%2,%3}, {%4,%5,%6,%7}, {%8,%9}, {%0,%1,%2,%3};" \
        : "+f"((c)[0]), "+f"((c)[1]), "+f"((c)[2]), "+f"((c)[3]) \
        : "r"((a)[0]), "r"((a)[1]), "r"((a)[2]), "r"((a)[3]), \
          "r"(b0), "r"(b1))

__device__ __forceinline__ __half toh(float x)  { return __float2half_rn(x); }

// ---------------------------------------------------------------------------
// Mega-prep (one launch, 4 roles decoded from blockIdx.x, 256 threads each):
//  role 0: denom + adj->half           blocks [0, 3072)
//  role 1: x0 transpose -> X0TH (half) blocks [3072, 7168)
//  role 2: Wg -> half                  blocks [7168, 8704)
//  role 3: Wo -> half                  blocks [8704, 10240)
// ---------------------------------------------------------------------------
constexpr int PREP_DEN = 3072;     // (H*B*S)/8 rows, 8 warps/block
constexpr int PREP_TRN = 4096;     // 16 x 16 x B
constexpr int PREP_WG  = 1536;     // H*L*D*D/4/256
constexpr int PREP_WO  = 1536;     // D*F/4/256
constexpr int PREP_BLOCKS = PREP_DEN + PREP_TRN + PREP_WG + PREP_WO;

__global__ void prep_kernel(const float* __restrict__ adj,
                            const float* __restrict__ x0,
                            const float* __restrict__ Wg,
                            const float* __restrict__ Wo,
                            float* __restrict__ den,
                            __half* __restrict__ adjH,
                            __half* __restrict__ X0TH,
                            __half* __restrict__ WgH,
                            __half* __restrict__ WoH)
{
    const int bid = blockIdx.x;
    const int tid = threadIdx.x;

    if (bid < PREP_DEN) {
        // denom + adj rounding (warp per row)
        int gw = (bid * 256 + tid) >> 5;
        int lane = tid & 31;
        const float4* p = (const float4*)(adj + (long)gw * S_);
        __half2* q = (__half2*)(adjH + (long)gw * S_);
        float s = 0.f;
        #pragma unroll 2
        for (int i = lane; i < S_ / 4; i += 32) {
            float4 v = p[i];
            s += v.x + v.y + v.z + v.w;
            q[2 * i]     = __floats2half2_rn(v.x, v.y);
            q[2 * i + 1] = __floats2half2_rn(v.z, v.w);
        }
        #pragma unroll
        for (int o = 16; o > 0; o >>= 1) s += __shfl_xor_sync(0xffffffffu, s, o);
        if (lane == 0) den[gw] = s + 1.0f;
    } else if (bid < PREP_DEN + PREP_TRN) {
        // x0 transpose -> X0TH[b][d][s]
        __shared__ __half t[32][33];
        int rel = bid - PREP_DEN;
        int s0 = (rel & 15) * 32;
        int d0 = ((rel >> 4) & 15) * 32;
        int bz = rel >> 8;
        const float* Xb = x0 + (long)bz * S_ * D_;
        __half* Tb = X0TH + (long)bz * D_ * S_;
        int tx = tid & 31, ty = tid >> 5;  // 32 x 8
        #pragma unroll
        for (int i = 0; i < 32; i += 8)
            t[ty + i][tx] = toh(Xb[(long)(s0 + ty + i) * D_ + d0 + tx]);
        __syncthreads();
        #pragma unroll
        for (int i = 0; i < 32; i += 8)
            Tb[(long)(d0 + ty + i) * S_ + s0 + tx] = t[tx][ty + i];
    } else if (bid < PREP_DEN + PREP_TRN + PREP_WG) {
        int i = (bid - PREP_DEN - PREP_TRN) * 256 + tid;
        float4 v = ((const float4*)Wg)[i];
        ((__half2*)WgH)[2 * i]     = __floats2half2_rn(v.x, v.y);
        ((__half2*)WgH)[2 * i + 1] = __floats2half2_rn(v.z, v.w);
    } else {
        int i = (bid - PREP_DEN - PREP_TRN - PREP_WG) * 256 + tid;
        float4 v = ((const float4*)Wo)[i];
        ((__half2*)WoH)[2 * i]     = __floats2half2_rn(v.x, v.y);
        ((__half2*)WoH)[2 * i + 1] = __floats2half2_rn(v.z, v.w);
    }
}

// ---------------------------------------------------------------------------
// FP16 mma.sync GEMM (fp32 accum): C[M,N] = A[M,K] * B[N,K]^T, K-major halves.
// CTA 128x128, 8 warps of 64x32, BK=64, 3-stage cp.async, one barrier/k-tile,
// B-fragment double buffer, 2 CTAs/SM. z encodes (head = z>>4, batch = z&15).
// MODE 0: Chalf = acc + epi[m][n]             (epi fp32 or fp16 per EPI_HALF)
// MODE 1: Chalf = relu((acc + biasScale*bias[n]) / denom[z,m])
//         WRITE_T: also write transposed half copy T[d][s] (layer-0 only)
// MODE 2: Cfloat = acc + bias[n] + epi[m][n]  (epi fp32)
// ---------------------------------------------------------------------------
constexpr int BM = 128, BN = 128, BK = 64;        // BK in halves (128 bytes)
constexpr int LDSROW = 72;                        // halves; 144B stride -> conflict-free
constexpr int STAGE_HALVES = 2 * BM * LDSROW;     // A + B = 18432
constexpr int STAGE_BYTES = STAGE_HALVES * 2;     // 36864
constexpr int NSTAGE = 3;
constexpr int SMEM_SZ = NSTAGE * STAGE_BYTES;     // 110592

template <int MODE, bool EPI_HALF, bool WRITE_T>
__global__ __launch_bounds__(256, 2)
void mma_gemm(const __half* __restrict__ A, const __half* __restrict__ Bm,
              void* __restrict__ C,
              int K, int lda, int ldb, int ldc,
              long aHead, long aBatch, long bHead, long bBatch,
              long cHead, long cBatch,
              const void* __restrict__ epi, int epiLd, long epiHead, long epiBatch,
              const float* __restrict__ bias, long biasHead, float biasScale,
              const float* __restrict__ denom, int denomStride,
              __half* __restrict__ T, long tHead, long tBatch)
{
    extern __shared__ char smemc[];
    const int tid = threadIdx.x;
    const int wid = tid >> 5, lane = tid & 31;
    const int bx = blockIdx.x, by = blockIdx.y, z = blockIdx.z;
    const int hz = z >> 4, bz = z & 15;

    const uint32_t sbase = smem_u32(smemc);

    const __half* Ab = A + (long)hz * aHead + (long)bz * aBatch + (long)(by * BM) * lda;
    const __half* Bb = Bm + (long)hz * bHead + (long)bz * bBatch + (long)(bx * BN) * ldb;

    // cp.async: 2 threads per 128B row, 4 x 16B chunks each
    const int ldrow = tid >> 1;
    const int ldh0  = (tid & 1) * 32;      // half offset within row

    auto load_stage = [&](int s, int kt) {
        const long k0 = (long)kt * BK + ldh0;
        const __half* ag = Ab + (long)ldrow * lda + k0;
        const __half* bg = Bb + (long)ldrow * ldb + k0;
        uint32_t da = sbase + (uint32_t)(s * STAGE_BYTES)
                    + (uint32_t)(ldrow * LDSROW + ldh0) * 2u;
        uint32_t db = da + (uint32_t)(BM * LDSROW) * 2u;
        #pragma unroll
        for (int i = 0; i < 4; ++i) {
            CP_ASYNC16(da + i * 16u, ag + i * 8);
            CP_ASYNC16(db + i * 16u, bg + i * 8);
        }
    };

    // warp tiling: 2 (m) x 4 (n); each warp 64x32
    const int m0 = (wid & 1) * 64;
    const int n0 = (wid >> 1) * 32;
    const int lq = lane >> 2;
    const int lr = lane & 3;

    const uint32_t aAddr0 = sbase
        + (uint32_t)((m0 + ((lane >> 3) & 1) * 8 + (lane & 7)) * LDSROW) * 2u
        + (uint32_t)(lane >> 4) * 16u;
    const uint32_t bAddr0 = sbase + (uint32_t)(BM * LDSROW) * 2u
        + (uint32_t)((n0 + (lane >> 4) * 8 + (lane & 7)) * LDSROW) * 2u
        + (uint32_t)((lane >> 3) & 1) * 16u;

    float c[4][4][4];
    #pragma unroll
    for (int mi = 0; mi < 4; ++mi)
        #pragma unroll
        for (int ni = 0; ni < 4; ++ni)
            #pragma unroll
            for (int j = 0; j < 4; ++j) c[mi][ni][j] = 0.f;

    const int numK = K >> 6;   // >= 8 for all our GEMMs

    load_stage(0, 0); CP_COMMIT();
    load_stage(1, 1); CP_COMMIT();

    for (int kt = 0; kt < numK; ++kt) {
        if (kt + 1 < numK) { CP_WAIT(1); } else { CP_WAIT(0); }
        __syncthreads();   // single barrier per k-tile (3-stage WAR covered)
        if (kt + 2 < numK) {
            load_stage((kt + 2) % NSTAGE, kt + 2);
            CP_COMMIT();
        }

        const uint32_t sOff = (uint32_t)(kt % NSTAGE) * STAGE_BYTES;
        uint32_t a[4][4], b[2][2][4];

        #pragma unroll
        for (int p = 0; p < 2; ++p)
            LDSM4(b[0][p][0], b[0][p][1], b[0][p][2], b[0][p][3],
                  bAddr0 + sOff + (uint32_t)p * (16u * LDSROW * 2u));

        #pragma unroll
        for (int ks = 0; ks < 4; ++ks) {          // k16 steps within BK=64
            const uint32_t kOff = sOff + (uint32_t)ks * 32u;   // 16 halves
            const int cur = ks & 1;
            if (ks < 3) {
                const uint32_t kOffN = sOff + (uint32_t)(ks + 1) * 32u;
                #pragma unroll
                for (int p = 0; p < 2; ++p)
                    LDSM4(b[cur ^ 1][p][0], b[cur ^ 1][p][1],
                          b[cur ^ 1][p][2], b[cur ^ 1][p][3],
                          bAddr0 + kOffN + (uint32_t)p * (16u * LDSROW * 2u));
            }
            #pragma unroll
            for (int mi = 0; mi < 4; ++mi)
                LDSM4(a[mi][0], a[mi][1], a[mi][2], a[mi][3],
                      aAddr0 + kOff + (uint32_t)mi * (16u * LDSROW * 2u));
            #pragma unroll
            for (int mi = 0; mi < 4; ++mi)
                #pragma unroll
                for (int ni = 0; ni < 4; ++ni)
                    MMA_F16(c[mi][ni], a[mi], b[cur][ni >> 1][(ni & 1) * 2],
                            b[cur][ni >> 1][(ni & 1) * 2 + 1]);
        }
    }

    // ---------------- epilogue ----------------
    const float* biasP = (MODE == 1 || MODE == 2) ? (bias + (long)hz * biasHead) : nullptr;

    // per-warp smem staging buffer for the transposed copy (reuses pipeline smem)
    __half* bufw = (__half*)smemc + wid * (64 * 33);
    if (WRITE_T) __syncthreads();   // all warps done with pipeline smem

    #pragma unroll
    for (int mi = 0; mi < 4; ++mi) {
        const int r0 = by * BM + m0 + mi * 16 + lq;
        float invd0 = 1.f, invd1 = 1.f;
        if (MODE == 1) {
            invd0 = 1.0f / denom[(long)z * denomStride + r0];
            invd1 = 1.0f / denom[(long)z * denomStride + r0 + 8];
        }
        #pragma unroll
        for (int ni = 0; ni < 4; ++ni) {
            const int col = bx * BN + n0 + ni * 8 + 2 * lr;
            float v00 = c[mi][ni][0], v01 = c[mi][ni][1];
            float v10 = c[mi][ni][2], v11 = c[mi][ni][3];
            if (MODE == 0) {
                if (EPI_HALF) {
                    const __half* Eb = (const __half*)epi
                        + (long)hz * epiHead + (long)bz * epiBatch;
                    float2 e0 = __half22float2(*(const __half2*)(Eb + (long)r0 * epiLd + col));
                    float2 e1 = __half22float2(*(const __half2*)(Eb + (long)(r0 + 8) * epiLd + col));
                    v00 += e0.x; v01 += e0.y; v10 += e1.x; v11 += e1.y;
                } else {
                    const float* Eb = (const float*)epi
                        + (long)hz * epiHead + (long)bz * epiBatch;
                    float2 e0 = *(const float2*)(Eb + (long)r0 * epiLd + col);
                    float2 e1 = *(const float2*)(Eb + (long)(r0 + 8) * epiLd + col);
                    v00 += e0.x; v01 += e0.y; v10 += e1.x; v11 += e1.y;
                }
                __half* Cb = (__half*)C + (long)hz * cHead + (long)bz * cBatch;
                *(__half2*)(Cb + (long)r0 * ldc + col)       = __floats2half2_rn(v00, v01);
                *(__half2*)(Cb + (long)(r0 + 8) * ldc + col) = __floats2half2_rn(v10, v11);
            } else if (MODE == 1) {
                const float b0 = biasScale * biasP[col];
                const float b1 = biasScale * biasP[col + 1];
                v00 = fmaxf((v00 + b0) * invd0, 0.f);
                v01 = fmaxf((v01 + b1) * invd0, 0.f);
                v10 = fmaxf((v10 + b0) * invd1, 0.f);
                v11 = fmaxf((v11 + b1) * invd1, 0.f);
                __half2 p0 = __floats2half2_rn(v00, v01);
                __half2 p1 = __floats2half2_rn(v10, v11);
                __half* Cb = (__half*)C + (long)hz * cHead + (long)bz * cBatch;
                *(__half2*)(Cb + (long)r0 * ldc + col)       = p0;
                *(__half2*)(Cb + (long)(r0 + 8) * ldc + col) = p1;
                if (WRITE_T) {
                    const int rl0 = mi * 16 + lq;          // 0..63 local row
                    const int cl  = ni * 8 + 2 * lr;       // 0..31 local col
                    bufw[rl0 * 33 + cl]           = __low2half(p0);
                    bufw[rl0 * 33 + cl + 1]       = __high2half(p0);
                    bufw[(rl0 + 8) * 33 + cl]     = __low2half(p1);
                    bufw[(rl0 + 8) * 33 + cl + 1] = __high2half(p1);
                }
            } else {  // MODE 2: fp32 output, fp32 epi (residual) + bias
                const float* Eb = (const float*)epi;
                float2 e0 = *(const float2*)(Eb + (long)r0 * epiLd + col);
                float2 e1 = *(const float2*)(Eb + (long)(r0 + 8) * epiLd + col);
                const float b0 = biasP[col], b1 = biasP[col + 1];
                v00 += e0.x + b0; v01 += e0.y + b1;
                v10 += e1.x + b0; v11 += e1.y + b1;
                float* Cb = (float*)C;
                float2 w0 = {v00, v01}, w1 = {v10, v11};
                *(float2*)(Cb + (long)r0 * ldc + col) = w0;
                *(float2*)(Cb + (long)(r0 + 8) * ldc + col) = w1;
            }
        }
    }

    if (WRITE_T) {
        __syncwarp();
        __half* Tb = T + (long)hz * tHead + (long)bz * tBatch;
        const int mG = by * BM + m0;     // global s base (64 rows)
        #pragma unroll 4
        for (int c2 = 0; c2 < 32; ++c2) {
            const long drow = (long)(bx * BN + n0 + c2) * S_;
            Tb[drow + mG + lane]      = bufw[lane * 33 + c2];
            Tb[drow + mG + 32 + lane] = bufw[(lane + 32) * 33 + c2];
        }
    }
}

// ---------------------------------------------------------------------------
extern "C" void kernel_launch(void* const* d_in, const int* in_sizes, int n_in,
                              void* d_out, int out_size)
{
    const float* adj = (const float*)d_in[0];   // [H,B,S,S]
    const float* x0  = (const float*)d_in[1];   // [B,S,D]
    const float* Wg  = (const float*)d_in[4];   // [H*L, D, D]
    const float* bg  = (const float*)d_in[5];   // [H*L, D]
    const float* Wo  = (const float*)d_in[6];   // [D, F]
    const float* bo  = (const float*)d_in[7];   // [D]
    float* out = (float*)d_out;                 // [B,S,D]

    __half *adjH, *AxH, *finH, *XTH, *X0TH, *WgH, *WoH;
    float* den;
    cudaGetSymbolAddress((void**)&adjH, g_adjH);
    cudaGetSymbolAddress((void**)&AxH,  g_AxH);
    cudaGetSymbolAddress((void**)&finH, g_finH);
    cudaGetSymbolAddress((void**)&XTH,  g_XTH);
    cudaGetSymbolAddress((void**)&X0TH, g_X0TH);
    cudaGetSymbolAddress((void**)&WgH,  g_WgH);
    cudaGetSymbolAddress((void**)&WoH,  g_WoH);
    cudaGetSymbolAddress((void**)&den,  g_denom);

    cudaFuncSetAttribute(mma_gemm<0, false, false>, cudaFuncAttributeMaxDynamicSharedMemorySize, SMEM_SZ);
    cudaFuncSetAttribute(mma_gemm<0, true,  false>, cudaFuncAttributeMaxDynamicSharedMemorySize, SMEM_SZ);
    cudaFuncSetAttribute(mma_gemm<1, false, false>, cudaFuncAttributeMaxDynamicSharedMemorySize, SMEM_SZ);
    cudaFuncSetAttribute(mma_gemm<1, false, true>,  cudaFuncAttributeMaxDynamicSharedMemorySize, SMEM_SZ);
    cudaFuncSetAttribute(mma_gemm<2, false, false>, cudaFuncAttributeMaxDynamicSharedMemorySize, SMEM_SZ);

    // ---- single fused prep launch ----
    prep_kernel<<<PREP_BLOCKS, 256>>>(adj, x0, Wg, Wo, den, adjH, X0TH, WgH, WoH);

    const long SS = (long)S_ * S_, SD = (long)S_ * D_, SF = (long)S_ * F_;
    const long DS = (long)D_ * S_, DD = (long)D_ * D_;

    for (int l = 0; l < L_; ++l) {
        // GEMM1 (all heads): AxH[h] = adj[h] @ X + X
        if (l == 0) {
            mma_gemm<0, false, false><<<dim3(4, 4, H_ * B_), 256, SMEM_SZ>>>(
                adjH, X0TH, AxH,
                S_, S_, S_, D_,
                (long)B_ * SS, SS, 0, DS, (long)B_ * SD, SD,
                x0, D_, 0, SD,
                nullptr, 0, 0.f,
                nullptr, 0,
                nullptr, 0, 0);
        } else {
            mma_gemm<0, true, false><<<dim3(4, 4, H_ * B_), 256, SMEM_SZ>>>(
                adjH, XTH, AxH,
                S_, S_, S_, D_,
                (long)B_ * SS, SS, (long)B_ * DS, DS, (long)B_ * SD, SD,
                finH, F_, (long)L_ * D_, SF,   // epi = prev layer output (fp16)
                nullptr, 0, 0.f,
                nullptr, 0,
                nullptr, 0, 0);
        }

        // GEMM2 (all heads): finH[.., (h*L+l)*D ..] = relu((AxH @ Wg^T + 2b)/den)
        // layer 0 also emits the transposed copy XTH for layer 1's GEMM1.
        if (l == 0) {
            mma_gemm<1, false, true><<<dim3(4, 4, H_ * B_), 256, SMEM_SZ>>>(
                AxH, WgH + (long)l * DD, finH + (long)l * D_,
                D_, D_, D_, F_,
                (long)B_ * SD, SD, (long)L_ * DD, 0, (long)L_ * D_, SF,
                nullptr, 0, 0, 0,
                bg + (long)l * D_, (long)L_ * D_, 2.0f,
                den, S_,
                XTH, (long)B_ * DS, DS);
        } else {
            mma_gemm<1, false, false><<<dim3(4, 4, H_ * B_), 256, SMEM_SZ>>>(
                AxH, WgH + (long)l * DD, finH + (long)l * D_,
                D_, D_, D_, F_,
                (long)B_ * SD, SD, (long)L_ * DD, 0, (long)L_ * D_, SF,
                nullptr, 0, 0, 0,
                bg + (long)l * D_, (long)L_ * D_, 2.0f,
                den, S_,
                nullptr, 0, 0);
        }
    }

    // Final: out = finH @ Wo^T + bo + x0   (M = B*S = 8192, K = F, fp32 out)
    mma_gemm<2, false, false><<<dim3(4, 64, 1), 256, SMEM_SZ>>>(
        finH, WoH, out,
        F_, F_, F_, D_,
        0, 0, 0, 0, 0, 0,
        x0, D_, 0, 0,
        bo, 0, 1.0f,
        nullptr, 0,
        nullptr, 0, 0);
}